// round 7
// baseline (speedup 1.0000x reference)
#include <cuda_runtime.h>
#include <cuda_bf16.h>
#include <math.h>
#include <cstdint>

#define HIDDEN 4096
#define HEADS 32
#define HDIM 128
#define BATCH 2
#define SEQ 960
#define MTOK (BATCH * SEQ)           // 1920
#define NHEADS_TOT (BATCH * HEADS)   // 64
#define KDIM HIDDEN                  // GEMM K = 4096
#define KCHUNK 32
#define NKT (KDIM / KCHUNK)          // 128 k-chunks

// ---------------- scratch (static device globals; no allocation) ----------------
__device__ float g_Qt[(size_t)MTOK * HIDDEN];
__device__ float g_Kt[(size_t)MTOK * HIDDEN];
__device__ float g_Vt[(size_t)MTOK * HIDDEN];
__device__ float g_Ctx[(size_t)MTOK * HIDDEN];
__device__ float g_S[(size_t)NHEADS_TOT * SEQ * SEQ];
__device__ __nv_bfloat16 g_Whi[(size_t)3 * HIDDEN * HIDDEN];  // fused qkv weight^T hi [3N][K]
__device__ __nv_bfloat16 g_Wlo[(size_t)3 * HIDDEN * HIDDEN];  // fused qkv weight^T lo [3N][K]
__device__ __nv_bfloat16 g_Ahi[(size_t)MTOK * HIDDEN];        // activation hi [M][K]
__device__ __nv_bfloat16 g_Alo[(size_t)MTOK * HIDDEN];        // activation lo [M][K]

struct COut { float* p[3]; };

// =====================================================================
// helpers
// =====================================================================
__device__ __forceinline__ uint32_t smem_to_u32(const void* p) {
    uint32_t a;
    asm("{ .reg .u64 t; cvta.to.shared.u64 t, %1; cvt.u32.u64 %0, t; }" : "=r"(a) : "l"(p));
    return a;
}
__device__ __forceinline__ void bsplit(float v, unsigned short& h, unsigned short& l) {
    __nv_bfloat16 hb = __float2bfloat16(v);
    float hf = __bfloat162float(hb);
    __nv_bfloat16 lb = __float2bfloat16(v - hf);
    h = __bfloat16_as_ushort(hb);
    l = __bfloat16_as_ushort(lb);
}
__device__ __forceinline__ void ldsm4(uint32_t* r, uint32_t addr) {
    asm volatile("ldmatrix.sync.aligned.m8n8.x4.shared.b16 {%0,%1,%2,%3}, [%4];"
                 : "=r"(r[0]), "=r"(r[1]), "=r"(r[2]), "=r"(r[3]) : "r"(addr));
}
__device__ __forceinline__ void mma_bf16(float* c, const uint32_t* a, uint32_t b0, uint32_t b1) {
    asm volatile(
        "mma.sync.aligned.m16n8k16.row.col.f32.bf16.bf16.f32 "
        "{%0,%1,%2,%3}, {%4,%5,%6,%7}, {%8,%9}, {%0,%1,%2,%3};"
        : "+f"(c[0]), "+f"(c[1]), "+f"(c[2]), "+f"(c[3])
        : "r"(a[0]), "r"(a[1]), "r"(a[2]), "r"(a[3]), "r"(b0), "r"(b1));
}
#define CP_ASYNC16(dst, src) \
    asm volatile("cp.async.cg.shared.global [%0], [%1], 16;" :: "r"(dst), "l"(src))
#define CP_COMMIT() asm volatile("cp.async.commit_group;" ::: "memory")

// =====================================================================
// Pre-split kernels
// =====================================================================
__global__ void __launch_bounds__(256) split_weight_t(
    const float* __restrict__ in, __nv_bfloat16* __restrict__ hi,
    __nv_bfloat16* __restrict__ lo)
{
    __shared__ float t[32][33];
    int tx = threadIdx.x & 31, ty = threadIdx.x >> 5;
    int x = blockIdx.x * 32 + tx;
    int y = blockIdx.y * 32 + ty;
#pragma unroll
    for (int j = 0; j < 32; j += 8)
        t[ty + j][tx] = in[(size_t)(y + j) * HIDDEN + x];
    __syncthreads();
    int xo = blockIdx.y * 32 + tx;
    int yo = blockIdx.x * 32 + ty;
#pragma unroll
    for (int j = 0; j < 32; j += 8) {
        unsigned short h, l;
        bsplit(t[tx][ty + j], h, l);
        size_t o = (size_t)(yo + j) * HIDDEN + xo;
        reinterpret_cast<unsigned short*>(hi)[o] = h;
        reinterpret_cast<unsigned short*>(lo)[o] = l;
    }
}

__global__ void __launch_bounds__(256) split_act(
    const float* __restrict__ in, __nv_bfloat16* __restrict__ hi,
    __nv_bfloat16* __restrict__ lo)
{
    size_t i = (size_t)blockIdx.x * 256 + threadIdx.x;
    float4 v = reinterpret_cast<const float4*>(in)[i];
    ushort4 h, l;
    bsplit(v.x, h.x, l.x); bsplit(v.y, h.y, l.y);
    bsplit(v.z, h.z, l.z); bsplit(v.w, h.w, l.w);
    reinterpret_cast<ushort4*>(hi)[i] = h;
    reinterpret_cast<ushort4*>(lo)[i] = l;
}

// =====================================================================
// bf16x3 GEMM: C[M][N] = A[M][K] @ W^T (W given as [N_total][K]).
// 128x128 tile, 256 threads, k-chunk 32, cp.async 2-stage, 80B rows.
// Inner loop: B-fragment PAIRS + term-major ordering -> 8 independent
// accumulators between same-acc reuses (hides HMMA latency).
// Per-accumulator term order (hh, hl, lh) identical to prior rounds.
// =====================================================================
#define ROWB 80
#define TILEB (128 * ROWB)                     // 10240
#define STAGEB (4 * TILEB)                     // 40960

template <int MB>
__global__ void __launch_bounds__(256, MB) gemm_bf16x3(
    const __nv_bfloat16* __restrict__ Ahi, const __nv_bfloat16* __restrict__ Alo,
    const __nv_bfloat16* __restrict__ Bhi, const __nv_bfloat16* __restrict__ Blo,
    COut cout)
{
    extern __shared__ char sm[];
    const int tid = threadIdx.x;
    const int lane = tid & 31;
    const int wid = tid >> 5;
    const int wm = wid & 3;
    const int wn = wid >> 2;
    const int bm = blockIdx.y * 128;
    const int bnG = blockIdx.x * 128;
    float* C = cout.p[blockIdx.x >> 5];
    const int bn = (blockIdx.x & 31) * 128;
    const uint32_t smem0 = smem_to_u32(sm);

    int id0 = tid, id1 = tid + 256;
    int r0 = id0 >> 2, c0 = id0 & 3;
    int r1 = id1 >> 2, c1 = id1 & 3;
    const __nv_bfloat16* Ah = Ahi + (size_t)bm * KDIM;
    const __nv_bfloat16* Al = Alo + (size_t)bm * KDIM;
    const __nv_bfloat16* Bh = Bhi + (size_t)bnG * KDIM;
    const __nv_bfloat16* Bl = Blo + (size_t)bnG * KDIM;

    auto stage_load = [&](int buf, int k0) {
        uint32_t base = smem0 + buf * STAGEB;
        uint32_t d0 = base + (uint32_t)(r0 * ROWB + c0 * 16);
        uint32_t d1 = base + (uint32_t)(r1 * ROWB + c1 * 16);
        size_t s0 = (size_t)r0 * KDIM + k0 + c0 * 8;
        size_t s1 = (size_t)r1 * KDIM + k0 + c1 * 8;
        CP_ASYNC16(d0,             Ah + s0);
        CP_ASYNC16(d0 + TILEB,     Al + s0);
        CP_ASYNC16(d0 + 2 * TILEB, Bh + s0);
        CP_ASYNC16(d0 + 3 * TILEB, Bl + s0);
        CP_ASYNC16(d1,             Ah + s1);
        CP_ASYNC16(d1 + TILEB,     Al + s1);
        CP_ASYNC16(d1 + 2 * TILEB, Bh + s1);
        CP_ASYNC16(d1 + 3 * TILEB, Bl + s1);
    };

    float acc[2][8][4];
#pragma unroll
    for (int i = 0; i < 2; i++)
#pragma unroll
        for (int j = 0; j < 8; j++)
#pragma unroll
            for (int q = 0; q < 4; q++) acc[i][j][q] = 0.f;

    const int lrow = (lane & 7) + ((lane >> 3) & 1) * 8;
    const uint32_t lcol = (uint32_t)(lane >> 4) * 16;

    stage_load(0, 0);
    CP_COMMIT();

    for (int t = 0; t < NKT; ++t) {
        if (t + 1 < NKT) {
            stage_load((t + 1) & 1, (t + 1) * KCHUNK);
            CP_COMMIT();
            asm volatile("cp.async.wait_group 1;" ::: "memory");
        } else {
            asm volatile("cp.async.wait_group 0;" ::: "memory");
        }
        __syncthreads();

        uint32_t base = smem0 + (t & 1) * STAGEB;
#pragma unroll
        for (int kk = 0; kk < 2; kk++) {
            uint32_t koff = (uint32_t)kk * 32;
            uint32_t ah[2][4], al[2][4];
#pragma unroll
            for (int mf = 0; mf < 2; mf++) {
                uint32_t addr = base + (uint32_t)((wm * 32 + mf * 16 + lrow) * ROWB) + lcol + koff;
                ldsm4(ah[mf], addr);
                ldsm4(al[mf], addr + TILEB);
            }
#pragma unroll
            for (int gp = 0; gp < 2; gp++) {        // pairs of B groups
                uint32_t bh[2][4], bl[2][4];
#pragma unroll
                for (int gg = 0; gg < 2; gg++) {
                    int g = gp * 2 + gg;
                    uint32_t addr = base + 2 * TILEB +
                        (uint32_t)((wn * 64 + g * 16 + lrow) * ROWB) + lcol + koff;
                    ldsm4(bh[gg], addr);
                    ldsm4(bl[gg], addr + TILEB);
                }
                // term hh: 8 independent accumulators
#pragma unroll
                for (int mf = 0; mf < 2; mf++)
#pragma unroll
                    for (int gg = 0; gg < 2; gg++)
#pragma unroll
                        for (int hf = 0; hf < 2; hf++) {
                            int nf = (gp * 2 + gg) * 2 + hf;
                            mma_bf16(acc[mf][nf], ah[mf], bh[gg][hf], bh[gg][hf + 2]);
                        }
                // term hl
#pragma unroll
                for (int mf = 0; mf < 2; mf++)
#pragma unroll
                    for (int gg = 0; gg < 2; gg++)
#pragma unroll
                        for (int hf = 0; hf < 2; hf++) {
                            int nf = (gp * 2 + gg) * 2 + hf;
                            mma_bf16(acc[mf][nf], ah[mf], bl[gg][hf], bl[gg][hf + 2]);
                        }
                // term lh
#pragma unroll
                for (int mf = 0; mf < 2; mf++)
#pragma unroll
                    for (int gg = 0; gg < 2; gg++)
#pragma unroll
                        for (int hf = 0; hf < 2; hf++) {
                            int nf = (gp * 2 + gg) * 2 + hf;
                            mma_bf16(acc[mf][nf], al[mf], bh[gg][hf], bh[gg][hf + 2]);
                        }
            }
        }
        __syncthreads();
    }

#pragma unroll
    for (int mf = 0; mf < 2; mf++) {
        int row = bm + wm * 32 + mf * 16 + (lane >> 2);
#pragma unroll
        for (int nf = 0; nf < 8; nf++) {
            int col = bn + wn * 64 + nf * 8 + (lane & 3) * 2;
            *reinterpret_cast<float2*>(&C[(size_t)row * HIDDEN + col]) =
                make_float2(acc[mf][nf][0], acc[mf][nf][1]);
            *reinterpret_cast<float2*>(&C[(size_t)(row + 8) * HIDDEN + col]) =
                make_float2(acc[mf][nf][2], acc[mf][nf][3]);
        }
    }
}

// ---------------- packed fp32x2 FMA (FFMA2) ----------------
__device__ __forceinline__ void ffma2(float2& c, float2 a, float2 b) {
    unsigned long long& uc = reinterpret_cast<unsigned long long&>(c);
    unsigned long long ua = reinterpret_cast<unsigned long long&>(a);
    unsigned long long ub = reinterpret_cast<unsigned long long&>(b);
    asm("fma.rn.f32x2 %0, %1, %2, %0;" : "+l"(uc) : "l"(ua), "l"(ub));
}

// =====================================================================
// RoPE: in-place on Q and K, layout [b, q, h*d]; position id = q index.
// =====================================================================
__global__ void rope_kernel(float* __restrict__ q, float* __restrict__ k) {
    int token = blockIdx.x;
    int pos = token % SEQ;
    float* qrow = q + (size_t)token * HIDDEN;
    float* krow = k + (size_t)token * HIDDEN;
    for (int idx = threadIdx.x; idx < HEADS * 64; idx += blockDim.x) {
        int h = idx >> 6;
        int d = idx & 63;
        float inv = exp2f(-(float)d * 0.20762050593046013f);
        float ang = (float)pos * inv;
        float s, c;
        sincosf(ang, &s, &c);
        int base = h * HDIM;
        float x1 = qrow[base + d], x2 = qrow[base + d + 64];
        qrow[base + d]      = x1 * c - x2 * s;
        qrow[base + d + 64] = x2 * c + x1 * s;
        x1 = krow[base + d]; x2 = krow[base + d + 64];
        krow[base + d]      = x1 * c - x2 * s;
        krow[base + d + 64] = x2 * c + x1 * s;
    }
}

// =====================================================================
// Scores: S[b,h,q,k] = Q·K / sqrt(128), lower-triangle tiles only.
// =====================================================================
__global__ void __launch_bounds__(128, 4) qk_kernel(
    const float* __restrict__ Qp, const float* __restrict__ Kp,
    float* __restrict__ Sp)
{
    if (blockIdx.x > blockIdx.y) return;
    int zb = blockIdx.z;
    int b = zb >> 5, h = zb & 31;
    int bm = blockIdx.y * 64;
    int bn = blockIdx.x * 64;
    const float* Aq = Qp + (size_t)b * SEQ * HIDDEN + h * HDIM;
    const float* Bk = Kp + (size_t)b * SEQ * HIDDEN + h * HDIM;
    float* Cs = Sp + (size_t)zb * SEQ * SEQ;

    __shared__ float As[16][64];
    __shared__ float Bs[16][64];
    int tid = threadIdx.x;
    int trow = (tid >> 4) << 3;
    int tcol = (tid & 15) << 2;

    float2 acc[8][2];
#pragma unroll
    for (int i = 0; i < 8; i++) { acc[i][0] = make_float2(0.f, 0.f); acc[i][1] = make_float2(0.f, 0.f); }

    for (int k0 = 0; k0 < HDIM; k0 += 16) {
#pragma unroll
        for (int i = 0; i < 2; i++) {
            int id = tid + i * 128;
            int row = id >> 2;
            int kq = (id & 3) << 2;
            float4 v = *reinterpret_cast<const float4*>(&Aq[(size_t)(bm + row) * HIDDEN + k0 + kq]);
            As[kq + 0][row] = v.x; As[kq + 1][row] = v.y;
            As[kq + 2][row] = v.z; As[kq + 3][row] = v.w;
            float4 w = *reinterpret_cast<const float4*>(&Bk[(size_t)(bn + row) * HIDDEN + k0 + kq]);
            Bs[kq + 0][row] = w.x; Bs[kq + 1][row] = w.y;
            Bs[kq + 2][row] = w.z; Bs[kq + 3][row] = w.w;
        }
        __syncthreads();
#pragma unroll
        for (int kk = 0; kk < 16; kk++) {
            float a[8]; float2 b2[2];
            *reinterpret_cast<float4*>(&a[0]) = *reinterpret_cast<float4*>(&As[kk][trow]);
            *reinterpret_cast<float4*>(&a[4]) = *reinterpret_cast<float4*>(&As[kk][trow + 4]);
            *reinterpret_cast<float4*>(&b2[0]) = *reinterpret_cast<float4*>(&Bs[kk][tcol]);
#pragma unroll
            for (int i = 0; i < 8; i++) {
                float2 ai = make_float2(a[i], a[i]);
                ffma2(acc[i][0], ai, b2[0]);
                ffma2(acc[i][1], ai, b2[1]);
            }
        }
        __syncthreads();
    }
    const float scale = 0.08838834764831845f;
#pragma unroll
    for (int i = 0; i < 8; i++) {
        float4 o = make_float4(acc[i][0].x * scale, acc[i][0].y * scale,
                               acc[i][1].x * scale, acc[i][1].y * scale);
        *reinterpret_cast<float4*>(&Cs[(size_t)(bm + trow + i) * SEQ + bn + tcol]) = o;
    }
}

// =====================================================================
// Landmark grouped softmax — one block per (b,h,q) row, in place.
// =====================================================================
__device__ __forceinline__ unsigned int ford(float f) {
    unsigned int u = __float_as_uint(f);
    return (u & 0x80000000u) ? ~u : (u | 0x80000000u);
}
__device__ __forceinline__ float funord(unsigned int u) {
    return __uint_as_float((u & 0x80000000u) ? (u & 0x7fffffffu) : ~u);
}

__global__ void __launch_bounds__(256) softmax_kernel(float* __restrict__ Sp) {
    int q = blockIdx.x;
    int zb = blockIdx.y;
    float* row = Sp + (size_t)zb * SEQ * SEQ + (size_t)q * SEQ;
    int qb = q >> 6;

    __shared__ unsigned int smax[16];
    __shared__ float ssum[16];
    __shared__ float lme[16];
    int tid = threadIdx.x;
    if (tid < 16) { smax[tid] = 0u; ssum[tid] = 0.f; lme[tid] = 0.f; }
    __syncthreads();

    float sv[4]; int gid[4];
#pragma unroll
    for (int i = 0; i < 4; i++) {
        int k = tid + i * 256;
        sv[i] = 0.f; gid[i] = -1;
        if (k <= q) {
            float v = row[k];
            int g = (((k >> 6) == qb) || ((k & 63) == 63)) ? 15 : (k >> 6);
            sv[i] = v; gid[i] = g;
            atomicMax(&smax[g], ford(v));
        }
    }
    __syncthreads();

    float ev[4];
#pragma unroll
    for (int i = 0; i < 4; i++) {
        ev[i] = 0.f;
        int k = tid + i * 256;
        if (k <= q) {
            float m = funord(smax[gid[i]]);
            float e = __expf(sv[i] - m);
            ev[i] = e;
            atomicAdd(&ssum[gid[i]], e);
            if (((k & 63) == 63) && ((k >> 6) < 15)) lme[k >> 6] = e;
        }
    }
    __syncthreads();

    float inv15 = __frcp_rn(ssum[15]);
#pragma unroll
    for (int i = 0; i < 4; i++) {
        int k = tid + i * 256;
        if (k >= SEQ) continue;
        float outv = 0.f;
        if (k <= q) {
            int g = gid[i];
            if (g == 15) {
                outv = ((k >> 6) == qb) ? ev[i] * inv15 : 0.f;
            } else {
                outv = (ev[i] / ssum[g]) * (lme[g] * inv15);
            }
        }
        row[k] = outv;
    }
}

// =====================================================================
// PV: Ctx[b,q,h*d] = P[b,h,q,k] @ V[b,k,h*d].
// =====================================================================
__global__ void __launch_bounds__(128, 4) pv_kernel(
    const float* __restrict__ Sp, const float* __restrict__ Vp,
    float* __restrict__ Cp)
{
    int zb = blockIdx.z;
    int b = zb >> 5, h = zb & 31;
    int bm = blockIdx.y * 64;
    const float* Ap = Sp + (size_t)zb * SEQ * SEQ;
    const float* Bv = Vp + (size_t)b * SEQ * HIDDEN + h * HDIM;
    float* Cc = Cp + (size_t)b * SEQ * HIDDEN + h * HDIM;

    __shared__ float As[16][64];
    __shared__ float Bs[16][128];
    int tid = threadIdx.x;
    int trow = (tid >> 4) << 3;
    int tcol = (tid & 15) << 3;

    float2 acc[8][4];
#pragma unroll
    for (int i = 0; i < 8; i++)
#pragma unroll
        for (int j = 0; j < 4; j++) acc[i][j] = make_float2(0.f, 0.f);

    int kend = bm + 64;
    for (int k0 = 0; k0 < kend; k0 += 16) {
#pragma unroll
        for (int i = 0; i < 2; i++) {
            int id = tid + i * 128;
            int rowi = id >> 2;
            int kq = (id & 3) << 2;
            float4 v = *reinterpret_cast<const float4*>(&Ap[(size_t)(bm + rowi) * SEQ + k0 + kq]);
            As[kq + 0][rowi] = v.x; As[kq + 1][rowi] = v.y;
            As[kq + 2][rowi] = v.z; As[kq + 3][rowi] = v.w;
        }
#pragma unroll
        for (int i = 0; i < 4; i++) {
            int id = tid + i * 128;
            int krow = id >> 5;
            int cg = (id & 31) << 2;
            *reinterpret_cast<float4*>(&Bs[krow][cg]) =
                *reinterpret_cast<const float4*>(&Bv[(size_t)(k0 + krow) * HIDDEN + cg]);
        }
        __syncthreads();
#pragma unroll
        for (int kk = 0; kk < 16; kk++) {
            float a[8]; float2 b[4];
            *reinterpret_cast<float4*>(&a[0]) = *reinterpret_cast<float4*>(&As[kk][trow]);
            *reinterpret_cast<float4*>(&a[4]) = *reinterpret_cast<float4*>(&As[kk][trow + 4]);
            *reinterpret_cast<float4*>(&b[0]) = *reinterpret_cast<float4*>(&Bs[kk][tcol]);
            *reinterpret_cast<float4*>(&b[2]) = *reinterpret_cast<float4*>(&Bs[kk][tcol + 4]);
#pragma unroll
            for (int i = 0; i < 8; i++) {
                float2 ai = make_float2(a[i], a[i]);
#pragma unroll
                for (int j = 0; j < 4; j++) ffma2(acc[i][j], ai, b[j]);
            }
        }
        __syncthreads();
    }
#pragma unroll
    for (int i = 0; i < 8; i++) {
        float* cr = &Cc[(size_t)(bm + trow + i) * HIDDEN + tcol];
        *reinterpret_cast<float4*>(&cr[0]) =
            make_float4(acc[i][0].x, acc[i][0].y, acc[i][1].x, acc[i][1].y);
        *reinterpret_cast<float4*>(&cr[4]) =
            make_float4(acc[i][2].x, acc[i][2].y, acc[i][3].x, acc[i][3].y);
    }
}

// =====================================================================
// Launch
// =====================================================================
extern "C" void kernel_launch(void* const* d_in, const int* in_sizes, int n_in,
                              void* d_out, int out_size) {
    const float* X  = (const float*)d_in[0];
    const float* wq = (const float*)d_in[1];
    const float* wk = (const float*)d_in[2];
    const float* wv = (const float*)d_in[3];
    const float* wo = (const float*)d_in[4];
    float* out = (float*)d_out;

    float *pQ, *pK, *pV, *pC, *pS;
    __nv_bfloat16 *pWhi, *pWlo, *pAhi, *pAlo;
    cudaGetSymbolAddress((void**)&pQ, g_Qt);
    cudaGetSymbolAddress((void**)&pK, g_Kt);
    cudaGetSymbolAddress((void**)&pV, g_Vt);
    cudaGetSymbolAddress((void**)&pC, g_Ctx);
    cudaGetSymbolAddress((void**)&pS, g_S);
    cudaGetSymbolAddress((void**)&pWhi, g_Whi);
    cudaGetSymbolAddress((void**)&pWlo, g_Wlo);
    cudaGetSymbolAddress((void**)&pAhi, g_Ahi);
    cudaGetSymbolAddress((void**)&pAlo, g_Alo);

    cudaFuncSetAttribute(gemm_bf16x3<1>, cudaFuncAttributeMaxDynamicSharedMemorySize,
                         2 * STAGEB);
    cudaFuncSetAttribute(gemm_bf16x3<2>, cudaFuncAttributeMaxDynamicSharedMemorySize,
                         2 * STAGEB);

    dim3 gT(HIDDEN / 32, HIDDEN / 32);                  // (128,128)
    int nAct = (MTOK * HIDDEN / 4) / 256;
    const size_t WSTRIDE = (size_t)HIDDEN * HIDDEN;

    split_act<<<nAct, 256>>>(X, pAhi, pAlo);
    split_weight_t<<<gT, 256>>>(wq, pWhi, pWlo);
    split_weight_t<<<gT, 256>>>(wk, pWhi + WSTRIDE, pWlo + WSTRIDE);
    split_weight_t<<<gT, 256>>>(wv, pWhi + 2 * WSTRIDE, pWlo + 2 * WSTRIDE);

    // fused QKV GEMM: 96 x-tiles over [12288][4096] fused weight
    COut qkv; qkv.p[0] = pQ; qkv.p[1] = pK; qkv.p[2] = pV;
    dim3 gQKV(3 * HIDDEN / 128, MTOK / 128);            // (96, 15)
    gemm_bf16x3<1><<<gQKV, 256, 2 * STAGEB>>>(pAhi, pAlo, pWhi, pWlo, qkv);

    rope_kernel<<<MTOK, 256>>>(pQ, pK);

    dim3 gQK(SEQ / 64, SEQ / 64, NHEADS_TOT);           // (15, 15, 64)
    qk_kernel<<<gQK, 128>>>(pQ, pK, pS);

    dim3 gSM(SEQ, NHEADS_TOT);                          // (960, 64)
    softmax_kernel<<<gSM, 256>>>(pS);

    dim3 gPV(1, SEQ / 64, NHEADS_TOT);                  // (1, 15, 64)
    pv_kernel<<<gPV, 128>>>(pS, pV, pC);

    // output GEMM: occ-2 instantiation (tail packing)
    split_act<<<nAct, 256>>>(pC, pAhi, pAlo);
    split_weight_t<<<gT, 256>>>(wo, pWhi, pWlo);
    COut oo; oo.p[0] = out; oo.p[1] = out; oo.p[2] = out;
    dim3 gO(HIDDEN / 128, MTOK / 128);                  // (32, 15)
    gemm_bf16x3<2><<<gO, 256, 2 * STAGEB>>>(pAhi, pAlo, pWhi, pWlo, oo);
}

// round 9
// speedup vs baseline: 1.0291x; 1.0291x over previous
#include <cuda_runtime.h>
#include <cuda_bf16.h>
#include <math.h>
#include <cstdint>

#define HIDDEN 4096
#define HEADS 32
#define HDIM 128
#define BATCH 2
#define SEQ 960
#define MTOK (BATCH * SEQ)           // 1920
#define NHEADS_TOT (BATCH * HEADS)   // 64
#define KDIM HIDDEN
#define KCHUNK 32
#define NKT (KDIM / KCHUNK)          // 128

// ---------------- scratch (static device globals; no allocation) ----------------
__device__ float g_Qt[(size_t)MTOK * HIDDEN];
__device__ float g_Kt[(size_t)MTOK * HIDDEN];
__device__ float g_Vt[(size_t)MTOK * HIDDEN];
__device__ float g_Ctx[(size_t)MTOK * HIDDEN];
__device__ float g_S[(size_t)NHEADS_TOT * SEQ * SEQ];
__device__ __nv_bfloat16 g_Whi[(size_t)4 * HIDDEN * HIDDEN];  // wq,wk,wv,wo ^T hi [N][K]
__device__ __nv_bfloat16 g_Wlo[(size_t)4 * HIDDEN * HIDDEN];
__device__ __nv_bfloat16 g_Ahi[(size_t)MTOK * HIDDEN];
__device__ __nv_bfloat16 g_Alo[(size_t)MTOK * HIDDEN];

struct COut { float* p[3]; };
struct WPtrs { const float* w[4]; };

// =====================================================================
// helpers
// =====================================================================
__device__ __forceinline__ uint32_t smem_to_u32(const void* p) {
    uint32_t a;
    asm("{ .reg .u64 t; cvta.to.shared.u64 t, %1; cvt.u32.u64 %0, t; }" : "=r"(a) : "l"(p));
    return a;
}
__device__ __forceinline__ void bsplit(float v, unsigned short& h, unsigned short& l) {
    __nv_bfloat16 hb = __float2bfloat16(v);
    float hf = __bfloat162float(hb);
    __nv_bfloat16 lb = __float2bfloat16(v - hf);
    h = __bfloat16_as_ushort(hb);
    l = __bfloat16_as_ushort(lb);
}
__device__ __forceinline__ void ldsm4(uint32_t* r, uint32_t addr) {
    asm volatile("ldmatrix.sync.aligned.m8n8.x4.shared.b16 {%0,%1,%2,%3}, [%4];"
                 : "=r"(r[0]), "=r"(r[1]), "=r"(r[2]), "=r"(r[3]) : "r"(addr));
}
__device__ __forceinline__ void mma_bf16(float* c, const uint32_t* a, uint32_t b0, uint32_t b1) {
    asm volatile(
        "mma.sync.aligned.m16n8k16.row.col.f32.bf16.bf16.f32 "
        "{%0,%1,%2,%3}, {%4,%5,%6,%7}, {%8,%9}, {%0,%1,%2,%3};"
        : "+f"(c[0]), "+f"(c[1]), "+f"(c[2]), "+f"(c[3])
        : "r"(a[0]), "r"(a[1]), "r"(a[2]), "r"(a[3]), "r"(b0), "r"(b1));
}
#define CP_ASYNC16(dst, src) \
    asm volatile("cp.async.cg.shared.global [%0], [%1], 16;" :: "r"(dst), "l"(src))
#define CP_COMMIT() asm volatile("cp.async.commit_group;" ::: "memory")

__device__ __forceinline__ float wredmax(float v) {
#pragma unroll
    for (int o = 16; o; o >>= 1) v = fmaxf(v, __shfl_xor_sync(0xffffffffu, v, o));
    return v;
}
__device__ __forceinline__ float wredsum(float v) {
#pragma unroll
    for (int o = 16; o; o >>= 1) v += __shfl_xor_sync(0xffffffffu, v, o);
    return v;
}

// ---------------- packed fp32x2 FMA ----------------
__device__ __forceinline__ void ffma2(float2& c, float2 a, float2 b) {
    unsigned long long& uc = reinterpret_cast<unsigned long long&>(c);
    unsigned long long ua = reinterpret_cast<unsigned long long&>(a);
    unsigned long long ub = reinterpret_cast<unsigned long long&>(b);
    asm("fma.rn.f32x2 %0, %1, %2, %0;" : "+l"(uc) : "l"(ua), "l"(ub));
}

// =====================================================================
// Pre-split kernels
// =====================================================================
__global__ void __launch_bounds__(256) split_weight4(
    WPtrs ws, __nv_bfloat16* __restrict__ hi, __nv_bfloat16* __restrict__ lo)
{
    __shared__ float t[32][33];
    const float* in = ws.w[blockIdx.z];
    hi += (size_t)blockIdx.z * HIDDEN * HIDDEN;
    lo += (size_t)blockIdx.z * HIDDEN * HIDDEN;
    int tx = threadIdx.x & 31, ty = threadIdx.x >> 5;
    int x = blockIdx.x * 32 + tx;
    int y = blockIdx.y * 32 + ty;
#pragma unroll
    for (int j = 0; j < 32; j += 8)
        t[ty + j][tx] = in[(size_t)(y + j) * HIDDEN + x];
    __syncthreads();
    int xo = blockIdx.y * 32 + tx;
    int yo = blockIdx.x * 32 + ty;
#pragma unroll
    for (int j = 0; j < 32; j += 8) {
        unsigned short h, l;
        bsplit(t[tx][ty + j], h, l);
        size_t o = (size_t)(yo + j) * HIDDEN + xo;
        reinterpret_cast<unsigned short*>(hi)[o] = h;
        reinterpret_cast<unsigned short*>(lo)[o] = l;
    }
}

__global__ void __launch_bounds__(256) split_act(
    const float* __restrict__ in, __nv_bfloat16* __restrict__ hi,
    __nv_bfloat16* __restrict__ lo)
{
    size_t i = (size_t)blockIdx.x * 256 + threadIdx.x;
    float4 v = reinterpret_cast<const float4*>(in)[i];
    ushort4 h, l;
    bsplit(v.x, h.x, l.x); bsplit(v.y, h.y, l.y);
    bsplit(v.z, h.z, l.z); bsplit(v.w, h.w, l.w);
    reinterpret_cast<ushort4*>(hi)[i] = h;
    reinterpret_cast<ushort4*>(lo)[i] = l;
}

// =====================================================================
// bf16x3 GEMM (legacy-HMMA-floor bound). occ-2.
// =====================================================================
#define ROWB 80
#define TILEB (128 * ROWB)
#define STAGEB (4 * TILEB)

template <int MB>
__global__ void __launch_bounds__(256, MB) gemm_bf16x3(
    const __nv_bfloat16* __restrict__ Ahi, const __nv_bfloat16* __restrict__ Alo,
    const __nv_bfloat16* __restrict__ Bhi, const __nv_bfloat16* __restrict__ Blo,
    COut cout)
{
    extern __shared__ char sm[];
    const int tid = threadIdx.x;
    const int lane = tid & 31;
    const int wid = tid >> 5;
    const int wm = wid & 3;
    const int wn = wid >> 2;
    const int bm = blockIdx.y * 128;
    const int bnG = blockIdx.x * 128;
    float* C = cout.p[blockIdx.x >> 5];
    const int bn = (blockIdx.x & 31) * 128;
    const uint32_t smem0 = smem_to_u32(sm);

    int r0 = tid >> 2, c0 = tid & 3;
    int r1 = (tid + 256) >> 2, c1 = tid & 3;
    const __nv_bfloat16* Ah = Ahi + (size_t)bm * KDIM;
    const __nv_bfloat16* Al = Alo + (size_t)bm * KDIM;
    const __nv_bfloat16* Bh = Bhi + (size_t)bnG * KDIM;
    const __nv_bfloat16* Bl = Blo + (size_t)bnG * KDIM;

    auto stage_load = [&](int buf, int k0) {
        uint32_t base = smem0 + buf * STAGEB;
        uint32_t d0 = base + (uint32_t)(r0 * ROWB + c0 * 16);
        uint32_t d1 = base + (uint32_t)(r1 * ROWB + c1 * 16);
        size_t s0 = (size_t)r0 * KDIM + k0 + c0 * 8;
        size_t s1 = (size_t)r1 * KDIM + k0 + c1 * 8;
        CP_ASYNC16(d0,             Ah + s0);
        CP_ASYNC16(d0 + TILEB,     Al + s0);
        CP_ASYNC16(d0 + 2 * TILEB, Bh + s0);
        CP_ASYNC16(d0 + 3 * TILEB, Bl + s0);
        CP_ASYNC16(d1,             Ah + s1);
        CP_ASYNC16(d1 + TILEB,     Al + s1);
        CP_ASYNC16(d1 + 2 * TILEB, Bh + s1);
        CP_ASYNC16(d1 + 3 * TILEB, Bl + s1);
    };

    float acc[2][8][4];
#pragma unroll
    for (int i = 0; i < 2; i++)
#pragma unroll
        for (int j = 0; j < 8; j++)
#pragma unroll
            for (int q = 0; q < 4; q++) acc[i][j][q] = 0.f;

    const int lrow = (lane & 7) + ((lane >> 3) & 1) * 8;
    const uint32_t lcol = (uint32_t)(lane >> 4) * 16;

    stage_load(0, 0);
    CP_COMMIT();

    for (int t = 0; t < NKT; ++t) {
        if (t + 1 < NKT) {
            stage_load((t + 1) & 1, (t + 1) * KCHUNK);
            CP_COMMIT();
            asm volatile("cp.async.wait_group 1;" ::: "memory");
        } else {
            asm volatile("cp.async.wait_group 0;" ::: "memory");
        }
        __syncthreads();

        uint32_t base = smem0 + (t & 1) * STAGEB;
#pragma unroll
        for (int kk = 0; kk < 2; kk++) {
            uint32_t koff = (uint32_t)kk * 32;
            uint32_t ah[2][4], al[2][4];
#pragma unroll
            for (int mf = 0; mf < 2; mf++) {
                uint32_t addr = base + (uint32_t)((wm * 32 + mf * 16 + lrow) * ROWB) + lcol + koff;
                ldsm4(ah[mf], addr);
                ldsm4(al[mf], addr + TILEB);
            }
#pragma unroll
            for (int g = 0; g < 4; g++) {
                uint32_t addr = base + 2 * TILEB +
                    (uint32_t)((wn * 64 + g * 16 + lrow) * ROWB) + lcol + koff;
                uint32_t bh[4], bl[4];
                ldsm4(bh, addr);
                ldsm4(bl, addr + TILEB);
#pragma unroll
                for (int mf = 0; mf < 2; mf++) {
#pragma unroll
                    for (int hf = 0; hf < 2; hf++) {
                        int nf = g * 2 + hf;
                        mma_bf16(acc[mf][nf], ah[mf], bh[hf], bh[hf + 2]);
                        mma_bf16(acc[mf][nf], ah[mf], bl[hf], bl[hf + 2]);
                        mma_bf16(acc[mf][nf], al[mf], bh[hf], bh[hf + 2]);
                    }
                }
            }
        }
        __syncthreads();
    }

#pragma unroll
    for (int mf = 0; mf < 2; mf++) {
        int row = bm + wm * 32 + mf * 16 + (lane >> 2);
#pragma unroll
        for (int nf = 0; nf < 8; nf++) {
            int col = bn + wn * 64 + nf * 8 + (lane & 3) * 2;
            *reinterpret_cast<float2*>(&C[(size_t)row * HIDDEN + col]) =
                make_float2(acc[mf][nf][0], acc[mf][nf][1]);
            *reinterpret_cast<float2*>(&C[(size_t)(row + 8) * HIDDEN + col]) =
                make_float2(acc[mf][nf][2], acc[mf][nf][3]);
        }
    }
}

// =====================================================================
// RoPE (unchanged)
// =====================================================================
__global__ void rope_kernel(float* __restrict__ q, float* __restrict__ k) {
    int token = blockIdx.x;
    int pos = token % SEQ;
    float* qrow = q + (size_t)token * HIDDEN;
    float* krow = k + (size_t)token * HIDDEN;
    for (int idx = threadIdx.x; idx < HEADS * 64; idx += blockDim.x) {
        int h = idx >> 6;
        int d = idx & 63;
        float inv = exp2f(-(float)d * 0.20762050593046013f);
        float ang = (float)pos * inv;
        float s, c;
        sincosf(ang, &s, &c);
        int base = h * HDIM;
        float x1 = qrow[base + d], x2 = qrow[base + d + 64];
        qrow[base + d]      = x1 * c - x2 * s;
        qrow[base + d + 64] = x2 * c + x1 * s;
        x1 = krow[base + d]; x2 = krow[base + d + 64];
        krow[base + d]      = x1 * c - x2 * s;
        krow[base + d + 64] = x2 * c + x1 * s;
    }
}

// =====================================================================
// QK scores (unchanged): lower-triangle 64x64 tiles.
// =====================================================================
__global__ void __launch_bounds__(128, 4) qk_kernel(
    const float* __restrict__ Qp, const float* __restrict__ Kp,
    float* __restrict__ Sp)
{
    if (blockIdx.x > blockIdx.y) return;
    int zb = blockIdx.z;
    int b = zb >> 5, h = zb & 31;
    int bm = blockIdx.y * 64;
    int bn = blockIdx.x * 64;
    const float* Aq = Qp + (size_t)b * SEQ * HIDDEN + h * HDIM;
    const float* Bk = Kp + (size_t)b * SEQ * HIDDEN + h * HDIM;
    float* Cs = Sp + (size_t)zb * SEQ * SEQ;

    __shared__ float As[16][64];
    __shared__ float Bs[16][64];
    int tid = threadIdx.x;
    int trow = (tid >> 4) << 3;
    int tcol = (tid & 15) << 2;

    float2 acc[8][2];
#pragma unroll
    for (int i = 0; i < 8; i++) { acc[i][0] = make_float2(0.f, 0.f); acc[i][1] = make_float2(0.f, 0.f); }

    for (int k0 = 0; k0 < HDIM; k0 += 16) {
#pragma unroll
        for (int i = 0; i < 2; i++) {
            int id = tid + i * 128;
            int row = id >> 2;
            int kq = (id & 3) << 2;
            float4 v = *reinterpret_cast<const float4*>(&Aq[(size_t)(bm + row) * HIDDEN + k0 + kq]);
            As[kq + 0][row] = v.x; As[kq + 1][row] = v.y;
            As[kq + 2][row] = v.z; As[kq + 3][row] = v.w;
            float4 w = *reinterpret_cast<const float4*>(&Bk[(size_t)(bn + row) * HIDDEN + k0 + kq]);
            Bs[kq + 0][row] = w.x; Bs[kq + 1][row] = w.y;
            Bs[kq + 2][row] = w.z; Bs[kq + 3][row] = w.w;
        }
        __syncthreads();
#pragma unroll
        for (int kk = 0; kk < 16; kk++) {
            float a[8]; float2 b2[2];
            *reinterpret_cast<float4*>(&a[0]) = *reinterpret_cast<float4*>(&As[kk][trow]);
            *reinterpret_cast<float4*>(&a[4]) = *reinterpret_cast<float4*>(&As[kk][trow + 4]);
            *reinterpret_cast<float4*>(&b2[0]) = *reinterpret_cast<float4*>(&Bs[kk][tcol]);
#pragma unroll
            for (int i = 0; i < 8; i++) {
                float2 ai = make_float2(a[i], a[i]);
                ffma2(acc[i][0], ai, b2[0]);
                ffma2(acc[i][1], ai, b2[1]);
            }
        }
        __syncthreads();
    }
    const float scale = 0.08838834764831845f;
#pragma unroll
    for (int i = 0; i < 8; i++) {
        float4 o = make_float4(acc[i][0].x * scale, acc[i][0].y * scale,
                               acc[i][1].x * scale, acc[i][1].y * scale);
        *reinterpret_cast<float4*>(&Cs[(size_t)(bm + trow + i) * SEQ + bn + tcol]) = o;
    }
}

// =====================================================================
// FUSED landmark softmax + PV.
// Grid (SEQ/32, NHEADS_TOT). 32 q-rows per CTA; P tile in SMEM.
// VSPITCH=144 covers the 9*m+j skew (max 142) with no row overlap.
// =====================================================================
#define PPITCH 961
#define VSPITCH 144
#define SMPV_BYTES ((32 * PPITCH + 16 * VSPITCH) * 4)

__global__ void __launch_bounds__(256) softmax_pv_kernel(
    const float* __restrict__ Sp, const float* __restrict__ Vp,
    float* __restrict__ Cp)
{
    extern __shared__ float dsm[];
    float* Pp = dsm;                     // [32][PPITCH]
    float* Vs = dsm + 32 * PPITCH;       // [16][VSPITCH] skewed: kk*144 + 9*m + j
    __shared__ float mg_s[32][16];
    __shared__ float coef_s[32][16];
    __shared__ float m15_s[32];
    __shared__ float inv15_s[32];

    const int zb = blockIdx.y;
    const int b = zb >> 5, h = zb & 31;
    const int bm = blockIdx.x * 32;
    const int qb = bm >> 6;
    const int kend = bm + 32;
    const int tid = threadIdx.x;
    const int lane = tid & 31;
    const int wid = tid >> 5;
    const float* Srow = Sp + (size_t)zb * SEQ * SEQ;
    const float NEGINF = -3.4e38f;

    // ---- Pass A: per-row group stats (warp per row, 8 warps x 4 rows) ----
    for (int rr = 0; rr < 4; rr++) {
        int r = wid * 4 + rr;
        int q = bm + r;
        int qrel = q & 63;
        const float* row = Srow + (size_t)q * SEQ;

        float mylm = NEGINF;   // landmark score of group `lane` (if lane<qb)
        float mysg = 1.f;      // group-`lane` denom
        for (int g = 0; g < qb; g++) {
            float2 v = *reinterpret_cast<const float2*>(&row[g * 64 + lane * 2]);
            float lm = __shfl_sync(0xffffffffu, v.y, 31);    // k=64g+63
            float mx = fmaxf(v.x, (lane == 31) ? NEGINF : v.y);
            float mg = wredmax(mx);
            float se = __expf(v.x - mg) + ((lane == 31) ? 0.f : __expf(v.y - mg));
            float sg = wredsum(se);
            if (g == lane) { mylm = lm; mysg = sg; }
            if (lane == 0) mg_s[r][g] = mg;
        }
        // own block (group 15): entries k<=q plus landmarks of earlier blocks
        float2 v = *reinterpret_cast<const float2*>(&row[qb * 64 + lane * 2]);
        float m15o = NEGINF;
        if (2 * lane <= qrel) m15o = v.x;
        if (2 * lane + 1 <= qrel) m15o = fmaxf(m15o, v.y);
        float m15 = wredmax(fmaxf(m15o, (lane < qb) ? mylm : NEGINF));
        float s15 = 0.f;
        if (2 * lane <= qrel) s15 += __expf(v.x - m15);
        if (2 * lane + 1 <= qrel) s15 += __expf(v.y - m15);
        float lme = (lane < qb) ? __expf(mylm - m15) : 0.f;
        s15 += lme;
        float sum15 = wredsum(s15);
        float inv15 = 1.f / sum15;
        if (lane < qb) coef_s[r][lane] = lme * inv15 / mysg;
        if (lane == 0) { m15_s[r] = m15; inv15_s[r] = inv15; }
    }
    __syncthreads();

    // ---- Pass B: materialize P[32][kend] ----
    for (int r = 0; r < 32; r++) {
        int q = bm + r;
        float m15 = m15_s[r];
        float inv15 = inv15_s[r];
        const float* row = Srow + (size_t)q * SEQ;
        for (int k = tid; k < kend; k += 256) {
            float s = row[k];
            int g = k >> 6;
            float p;
            if (g == qb) {
                p = (k <= q) ? __expf(s - m15) * inv15 : 0.f;
            } else if ((k & 63) == 63) {
                p = 0.f;
            } else {
                p = __expf(s - mg_s[r][g]) * coef_s[r][g];
            }
            Pp[r * PPITCH + k] = p;
        }
    }

    // ---- Pass C: Ctx[32][128] = P @ V ----
    const int trow = (tid >> 4) * 2;     // 2 rows
    const int tcol = (tid & 15) * 8;     // 8 cols
    const int m = tid & 15;
    float2 acc[2][4];
#pragma unroll
    for (int i = 0; i < 2; i++)
#pragma unroll
        for (int j = 0; j < 4; j++) acc[i][j] = make_float2(0.f, 0.f);

    const float* Vbase = Vp + (size_t)b * SEQ * HIDDEN + h * HDIM;
    for (int k0 = 0; k0 < kend; k0 += 16) {
        __syncthreads();
        {   // stage V[16][128] skewed
            int kk = tid >> 4;
            const float* vsrc = Vbase + (size_t)(k0 + kk) * HIDDEN + m * 8;
            float4 va = *reinterpret_cast<const float4*>(vsrc);
            float4 vb = *reinterpret_cast<const float4*>(vsrc + 4);
            float* vd = Vs + kk * VSPITCH + 9 * m;
            vd[0] = va.x; vd[1] = va.y; vd[2] = va.z; vd[3] = va.w;
            vd[4] = vb.x; vd[5] = vb.y; vd[6] = vb.z; vd[7] = vb.w;
        }
        __syncthreads();
#pragma unroll
        for (int kk = 0; kk < 16; kk++) {
            int k = k0 + kk;
            float a0 = Pp[trow * PPITCH + k];
            float a1 = Pp[(trow + 1) * PPITCH + k];
            const float* vd = Vs + kk * VSPITCH + 9 * m;
            float2 av0 = make_float2(a0, a0);
            float2 av1 = make_float2(a1, a1);
#pragma unroll
            for (int j = 0; j < 4; j++) {
                float2 bv = make_float2(vd[2 * j], vd[2 * j + 1]);
                ffma2(acc[0][j], av0, bv);
                ffma2(acc[1][j], av1, bv);
            }
        }
    }
#pragma unroll
    for (int i = 0; i < 2; i++) {
        float* cr = Cp + (size_t)(b * SEQ + bm + trow + i) * HIDDEN + h * HDIM + tcol;
        *reinterpret_cast<float4*>(cr) =
            make_float4(acc[i][0].x, acc[i][0].y, acc[i][1].x, acc[i][1].y);
        *reinterpret_cast<float4*>(cr + 4) =
            make_float4(acc[i][2].x, acc[i][2].y, acc[i][3].x, acc[i][3].y);
    }
}

// =====================================================================
// Launch
// =====================================================================
extern "C" void kernel_launch(void* const* d_in, const int* in_sizes, int n_in,
                              void* d_out, int out_size) {
    const float* X  = (const float*)d_in[0];
    const float* wq = (const float*)d_in[1];
    const float* wk = (const float*)d_in[2];
    const float* wv = (const float*)d_in[3];
    const float* wo = (const float*)d_in[4];
    float* out = (float*)d_out;

    float *pQ, *pK, *pV, *pC, *pS;
    __nv_bfloat16 *pWhi, *pWlo, *pAhi, *pAlo;
    cudaGetSymbolAddress((void**)&pQ, g_Qt);
    cudaGetSymbolAddress((void**)&pK, g_Kt);
    cudaGetSymbolAddress((void**)&pV, g_Vt);
    cudaGetSymbolAddress((void**)&pC, g_Ctx);
    cudaGetSymbolAddress((void**)&pS, g_S);
    cudaGetSymbolAddress((void**)&pWhi, g_Whi);
    cudaGetSymbolAddress((void**)&pWlo, g_Wlo);
    cudaGetSymbolAddress((void**)&pAhi, g_Ahi);
    cudaGetSymbolAddress((void**)&pAlo, g_Alo);

    cudaFuncSetAttribute(gemm_bf16x3<2>, cudaFuncAttributeMaxDynamicSharedMemorySize,
                         2 * STAGEB);
    cudaFuncSetAttribute(softmax_pv_kernel, cudaFuncAttributeMaxDynamicSharedMemorySize,
                         SMPV_BYTES);

    int nAct = (MTOK * HIDDEN / 4) / 256;
    const size_t WSTRIDE = (size_t)HIDDEN * HIDDEN;

    split_act<<<nAct, 256>>>(X, pAhi, pAlo);
    WPtrs ws; ws.w[0] = wq; ws.w[1] = wk; ws.w[2] = wv; ws.w[3] = wo;
    dim3 gT(HIDDEN / 32, HIDDEN / 32, 4);
    split_weight4<<<gT, 256>>>(ws, pWhi, pWlo);

    // fused QKV GEMM (occ-2)
    COut qkv; qkv.p[0] = pQ; qkv.p[1] = pK; qkv.p[2] = pV;
    dim3 gQKV(3 * HIDDEN / 128, MTOK / 128);
    gemm_bf16x3<2><<<gQKV, 256, 2 * STAGEB>>>(pAhi, pAlo, pWhi, pWlo, qkv);

    rope_kernel<<<MTOK, 256>>>(pQ, pK);

    dim3 gQK(SEQ / 64, SEQ / 64, NHEADS_TOT);
    qk_kernel<<<gQK, 128>>>(pQ, pK, pS);

    dim3 gPV(SEQ / 32, NHEADS_TOT);
    softmax_pv_kernel<<<gPV, 256, SMPV_BYTES>>>(pS, pV, pC);

    // output GEMM (occ-2)
    split_act<<<nAct, 256>>>(pC, pAhi, pAlo);
    COut oo; oo.p[0] = out; oo.p[1] = out; oo.p[2] = out;
    dim3 gO(HIDDEN / 128, MTOK / 128);
    gemm_bf16x3<2><<<gO, 256, 2 * STAGEB>>>(pAhi, pAlo,
                                            pWhi + 3 * WSTRIDE, pWlo + 3 * WSTRIDE, oo);
}